// round 1
// baseline (speedup 1.0000x reference)
#include <cuda_runtime.h>
#include <cstddef>

// ---------------------------------------------------------------------------
// Problem constants: B=4, T=2048, C=2048, H=16, S=128
// ---------------------------------------------------------------------------
#define MDIM (4 * 2048)   // B*T = 8192
#define NDIM 2048         // C
#define KDIM 2048         // C
#define HH 16
#define SS 128
#define TT 2048

// Scratch (allocation-free: __device__ globals)
__device__ float g_k[(size_t)MDIM * NDIM];
__device__ float g_v[(size_t)MDIM * NDIM];
__device__ float g_r[(size_t)MDIM * NDIM];

// ---------------------------------------------------------------------------
// GEMM: C[M,N] = A[M,K] @ B[N,K]^T   (all row-major; inner product of rows)
// 128x128 tile, BK=8, 256 threads, 8x8 per thread (split 4+4 mapping for
// conflict-free LDS.128), global->reg->smem double buffering.
// M,N,K are multiples of 128/8 here, so no bounds checks.
// ---------------------------------------------------------------------------
#define BM 128
#define BN 128
#define BK 8

__global__ __launch_bounds__(256, 2) void gemm_nt(
    const float* __restrict__ A, const float* __restrict__ B,
    float* __restrict__ C, int M, int N, int K)
{
    __shared__ float As[BK][BM];
    __shared__ float Bs[BK][BN];

    const int tid   = threadIdx.x;
    const int tx    = tid & 15;        // 0..15 -> N direction
    const int ty    = tid >> 4;        // 0..15 -> M direction
    const int a_row = tid >> 1;        // 0..127
    const int a_col = (tid & 1) << 2;  // 0 or 4

    const float* Aptr = A + (size_t)(blockIdx.y * BM + a_row) * K + a_col;
    const float* Bptr = B + (size_t)(blockIdx.x * BN + a_row) * K + a_col;

    float acc[8][8];
#pragma unroll
    for (int i = 0; i < 8; i++)
#pragma unroll
        for (int j = 0; j < 8; j++) acc[i][j] = 0.f;

    float4 a4 = *(const float4*)Aptr;
    float4 b4 = *(const float4*)Bptr;

    for (int k0 = 0; k0 < K; k0 += BK) {
        As[a_col + 0][a_row] = a4.x;
        As[a_col + 1][a_row] = a4.y;
        As[a_col + 2][a_row] = a4.z;
        As[a_col + 3][a_row] = a4.w;
        Bs[a_col + 0][a_row] = b4.x;
        Bs[a_col + 1][a_row] = b4.y;
        Bs[a_col + 2][a_row] = b4.z;
        Bs[a_col + 3][a_row] = b4.w;
        __syncthreads();

        if (k0 + BK < K) {
            Aptr += BK;
            Bptr += BK;
            a4 = *(const float4*)Aptr;
            b4 = *(const float4*)Bptr;
        }

#pragma unroll
        for (int kk = 0; kk < BK; kk++) {
            float4 ar0 = *(const float4*)&As[kk][ty * 4];
            float4 ar1 = *(const float4*)&As[kk][64 + ty * 4];
            float4 br0 = *(const float4*)&Bs[kk][tx * 4];
            float4 br1 = *(const float4*)&Bs[kk][64 + tx * 4];
            float ar[8] = {ar0.x, ar0.y, ar0.z, ar0.w, ar1.x, ar1.y, ar1.z, ar1.w};
            float br[8] = {br0.x, br0.y, br0.z, br0.w, br1.x, br1.y, br1.z, br1.w};
#pragma unroll
            for (int i = 0; i < 8; i++)
#pragma unroll
                for (int j = 0; j < 8; j++)
                    acc[i][j] = fmaf(ar[i], br[j], acc[i][j]);
        }
        __syncthreads();
    }

#pragma unroll
    for (int i = 0; i < 8; i++) {
        int mrow = blockIdx.y * BM + ((i < 4) ? (ty * 4 + i) : (64 + ty * 4 + (i - 4)));
        float* Crow = C + (size_t)mrow * N + blockIdx.x * BN;
        *(float4*)&Crow[tx * 4]      = make_float4(acc[i][0], acc[i][1], acc[i][2], acc[i][3]);
        *(float4*)&Crow[64 + tx * 4] = make_float4(acc[i][4], acc[i][5], acc[i][6], acc[i][7]);
    }
}

// ---------------------------------------------------------------------------
// WKV recurrence + sigmoid gating, fused. One block per (h,b) pair, 128
// threads = S channels. Chunked smem staging of k/v/r (CH timesteps) to
// amortize DRAM latency; output written in-place into the r buffer.
// ---------------------------------------------------------------------------
#define CH 32

__global__ __launch_bounds__(128) void wkv_sigmoid(
    const float* __restrict__ k, const float* __restrict__ v,
    float* __restrict__ r,                      // in: r ; out: sigmoid(r)*wkv
    const float* __restrict__ time_decay,
    const float* __restrict__ time_first)
{
    __shared__ float sk[CH][SS];
    __shared__ float sv[CH][SS];
    __shared__ float sr[CH][SS];

    const int h = blockIdx.x;
    const int b = blockIdx.y;
    const int s = threadIdx.x;
    const int C = HH * SS;

    const float decay = expf(-expf(time_decay[h * SS + s]));
    const float first = expf(time_first[h * SS + s]);

    const size_t base = ((size_t)b * TT) * C + (size_t)h * SS;

    float num = 0.f, den = 0.f;

    for (int t0 = 0; t0 < TT; t0 += CH) {
        __syncthreads();
        // cooperative chunk load: CH*SS floats per array, float4 vectorized
#pragma unroll
        for (int i = threadIdx.x; i < CH * SS / 4; i += 128) {
            int tt = i >> 5;            // SS/4 == 32
            int s4 = (i & 31) << 2;
            size_t g = base + (size_t)(t0 + tt) * C + s4;
            *(float4*)&sk[tt][s4] = *(const float4*)&k[g];
            *(float4*)&sv[tt][s4] = *(const float4*)&v[g];
            *(float4*)&sr[tt][s4] = *(const float4*)&r[g];
        }
        __syncthreads();

        float* outp = r + base + (size_t)t0 * C + s;
#pragma unroll 4
        for (int tt = 0; tt < CH; tt++) {
            float kk = fminf(fmaxf(sk[tt][s], -10.f), 10.f);
            float w  = __expf(kk);
            if (t0 + tt == 0) w *= first;
            num = fmaf(decay, num, w * sv[tt][s]);
            den = fmaf(decay, den, w);
            float rr  = sr[tt][s];
            float sig = 1.f / (1.f + __expf(-rr));
            outp[(size_t)tt * C] = sig * (num / (den + 1e-6f));
        }
    }
}

// ---------------------------------------------------------------------------
// Launch: 3 GEMMs (k,v,r), fused recurrence (in-place into r), final GEMM.
// ---------------------------------------------------------------------------
extern "C" void kernel_launch(void* const* d_in, const int* in_sizes, int n_in,
                              void* d_out, int out_size)
{
    const float* x  = (const float*)d_in[0];
    const float* Wk = (const float*)d_in[1];
    const float* Wv = (const float*)d_in[2];
    const float* Wr = (const float*)d_in[3];
    const float* Wo = (const float*)d_in[4];
    const float* td = (const float*)d_in[5];
    const float* tf = (const float*)d_in[6];
    float* out = (float*)d_out;

    float *pk, *pv, *pr;
    cudaGetSymbolAddress((void**)&pk, g_k);
    cudaGetSymbolAddress((void**)&pv, g_v);
    cudaGetSymbolAddress((void**)&pr, g_r);

    dim3 grid(NDIM / BN, MDIM / BM);
    dim3 block(256);

    gemm_nt<<<grid, block>>>(x, Wk, pk, MDIM, NDIM, KDIM);
    gemm_nt<<<grid, block>>>(x, Wv, pv, MDIM, NDIM, KDIM);
    gemm_nt<<<grid, block>>>(x, Wr, pr, MDIM, NDIM, KDIM);

    wkv_sigmoid<<<dim3(HH, 4), 128>>>(pk, pv, pr, td, tf);

    gemm_nt<<<grid, block>>>(pr, Wo, out, MDIM, NDIM, KDIM);
}

// round 2
// speedup vs baseline: 2.3499x; 2.3499x over previous
#include <cuda_runtime.h>
#include <cstdint>
#include <cstddef>

// ---------------------------------------------------------------------------
// Problem constants: B=4, T=2048, C=2048, H=16, S=128
// ---------------------------------------------------------------------------
#define MDIM 8192   // B*T
#define NDIM 2048   // C
#define KDIM 2048   // C
#define HH 16
#define SS 128
#define TT 2048

// Scratch (allocation-free: __device__ globals)
__device__ float g_k[(size_t)MDIM * NDIM];
__device__ float g_v[(size_t)MDIM * NDIM];
__device__ float g_r[(size_t)MDIM * NDIM];

// ---------------------------------------------------------------------------
// TF32 tensor-core GEMM: C[M,N] = A[M,K] @ B[N,K]^T (row-major, K-contig both)
// Block tile 128x128x16, 256 threads = 8 warps (2 M x 4 N), warp tile 64x32.
// mma.sync.m16n8k8.tf32. smem row-major with stride 20 (conflict-free frags).
// Double-buffered smem, reg-staged global loads, tf32 convert at store time.
// ---------------------------------------------------------------------------
#define BM 128
#define BN 128
#define BK 16
#define BKP 20

__device__ __forceinline__ uint32_t f2tf32(float x) {
    uint32_t r;
    asm("cvt.rna.tf32.f32 %0, %1;" : "=r"(r) : "f"(x));
    return r;
}

#define MMA_TF32(d, a, b)                                                  \
    asm volatile(                                                          \
        "mma.sync.aligned.m16n8k8.row.col.f32.tf32.tf32.f32 "              \
        "{%0,%1,%2,%3}, {%4,%5,%6,%7}, {%8,%9}, {%0,%1,%2,%3};"            \
        : "+f"(d[0]), "+f"(d[1]), "+f"(d[2]), "+f"(d[3])                   \
        : "r"(a[0]), "r"(a[1]), "r"(a[2]), "r"(a[3]), "r"(b[0]), "r"(b[1]))

__global__ __launch_bounds__(256, 2) void gemm_nt_tf32(
    const float* __restrict__ A, const float* __restrict__ B,
    float* __restrict__ C, int M, int N, int K)
{
    __shared__ uint32_t As[2][BM * BKP];
    __shared__ uint32_t Bs[2][BN * BKP];

    const int tid  = threadIdx.x;
    const int lane = tid & 31;
    const int wid  = tid >> 5;
    const int wm   = (wid & 1) * 64;   // warp M offset in block tile
    const int wn   = (wid >> 1) * 32;  // warp N offset
    const int g    = lane >> 2;        // 0..7
    const int t4   = lane & 3;         // 0..3

    // global loader mapping: thread covers rows r0 and r0+64, 4 floats at c0
    const int r0 = tid >> 2;           // 0..63
    const int c0 = (tid & 3) * 4;      // 0,4,8,12

    const float* Ap0 = A + (size_t)(blockIdx.y * BM + r0) * K + c0;
    const float* Ap1 = Ap0 + (size_t)64 * K;
    const float* Bp0 = B + (size_t)(blockIdx.x * BN + r0) * K + c0;
    const float* Bp1 = Bp0 + (size_t)64 * K;

    float acc[4][4][4];
#pragma unroll
    for (int mi = 0; mi < 4; mi++)
#pragma unroll
        for (int ni = 0; ni < 4; ni++)
#pragma unroll
            for (int j = 0; j < 4; j++) acc[mi][ni][j] = 0.f;

    float4 ra0 = *(const float4*)Ap0;
    float4 ra1 = *(const float4*)Ap1;
    float4 rb0 = *(const float4*)Bp0;
    float4 rb1 = *(const float4*)Bp1;

    const int KT = K / BK;
    int s = 0;

    for (int kt = 0; kt < KT; kt++) {
        // store staged regs into smem[s] with tf32 conversion
        uint32_t* as = As[s];
        uint32_t* bs = Bs[s];
        as[(r0)      * BKP + c0 + 0] = f2tf32(ra0.x);
        as[(r0)      * BKP + c0 + 1] = f2tf32(ra0.y);
        as[(r0)      * BKP + c0 + 2] = f2tf32(ra0.z);
        as[(r0)      * BKP + c0 + 3] = f2tf32(ra0.w);
        as[(r0 + 64) * BKP + c0 + 0] = f2tf32(ra1.x);
        as[(r0 + 64) * BKP + c0 + 1] = f2tf32(ra1.y);
        as[(r0 + 64) * BKP + c0 + 2] = f2tf32(ra1.z);
        as[(r0 + 64) * BKP + c0 + 3] = f2tf32(ra1.w);
        bs[(r0)      * BKP + c0 + 0] = f2tf32(rb0.x);
        bs[(r0)      * BKP + c0 + 1] = f2tf32(rb0.y);
        bs[(r0)      * BKP + c0 + 2] = f2tf32(rb0.z);
        bs[(r0)      * BKP + c0 + 3] = f2tf32(rb0.w);
        bs[(r0 + 64) * BKP + c0 + 0] = f2tf32(rb1.x);
        bs[(r0 + 64) * BKP + c0 + 1] = f2tf32(rb1.y);
        bs[(r0 + 64) * BKP + c0 + 2] = f2tf32(rb1.z);
        bs[(r0 + 64) * BKP + c0 + 3] = f2tf32(rb1.w);
        __syncthreads();

        // prefetch next K tile into regs
        if (kt + 1 < KT) {
            const int off = (kt + 1) * BK;
            ra0 = *(const float4*)(Ap0 + off);
            ra1 = *(const float4*)(Ap1 + off);
            rb0 = *(const float4*)(Bp0 + off);
            rb1 = *(const float4*)(Bp1 + off);
        }

        // compute: 2 k8 sub-steps
#pragma unroll
        for (int ks = 0; ks < 2; ks++) {
            const int k0 = ks * 8;
            uint32_t af[4][4];
            uint32_t bf[4][2];
#pragma unroll
            for (int mi = 0; mi < 4; mi++) {
                const int ra = wm + mi * 16 + g;
                af[mi][0] = as[(ra)     * BKP + k0 + t4];
                af[mi][1] = as[(ra + 8) * BKP + k0 + t4];
                af[mi][2] = as[(ra)     * BKP + k0 + t4 + 4];
                af[mi][3] = as[(ra + 8) * BKP + k0 + t4 + 4];
            }
#pragma unroll
            for (int ni = 0; ni < 4; ni++) {
                const int cn = wn + ni * 8 + g;
                bf[ni][0] = bs[cn * BKP + k0 + t4];
                bf[ni][1] = bs[cn * BKP + k0 + t4 + 4];
            }
#pragma unroll
            for (int mi = 0; mi < 4; mi++)
#pragma unroll
                for (int ni = 0; ni < 4; ni++)
                    MMA_TF32(acc[mi][ni], af[mi], bf[ni]);
        }
        s ^= 1;
    }

    // epilogue: fragment layout -> global (float2 stores, coalesced per quad)
#pragma unroll
    for (int mi = 0; mi < 4; mi++) {
#pragma unroll
        for (int ni = 0; ni < 4; ni++) {
            const int row = blockIdx.y * BM + wm + mi * 16 + g;
            const int col = blockIdx.x * BN + wn + ni * 8 + 2 * t4;
            *(float2*)&C[(size_t)row * N + col] =
                make_float2(acc[mi][ni][0], acc[mi][ni][1]);
            *(float2*)&C[(size_t)(row + 8) * N + col] =
                make_float2(acc[mi][ni][2], acc[mi][ni][3]);
        }
    }
}

// ---------------------------------------------------------------------------
// WKV recurrence + sigmoid gating (unchanged from R1; 328us, revisit later)
// ---------------------------------------------------------------------------
#define CH 32

__global__ __launch_bounds__(128) void wkv_sigmoid(
    const float* __restrict__ k, const float* __restrict__ v,
    float* __restrict__ r,
    const float* __restrict__ time_decay,
    const float* __restrict__ time_first)
{
    __shared__ float sk[CH][SS];
    __shared__ float sv[CH][SS];
    __shared__ float sr[CH][SS];

    const int h = blockIdx.x;
    const int b = blockIdx.y;
    const int s = threadIdx.x;
    const int C = HH * SS;

    const float decay = expf(-expf(time_decay[h * SS + s]));
    const float first = expf(time_first[h * SS + s]);

    const size_t base = ((size_t)b * TT) * C + (size_t)h * SS;

    float num = 0.f, den = 0.f;

    for (int t0 = 0; t0 < TT; t0 += CH) {
        __syncthreads();
#pragma unroll
        for (int i = threadIdx.x; i < CH * SS / 4; i += 128) {
            int tt = i >> 5;
            int s4 = (i & 31) << 2;
            size_t gofs = base + (size_t)(t0 + tt) * C + s4;
            *(float4*)&sk[tt][s4] = *(const float4*)&k[gofs];
            *(float4*)&sv[tt][s4] = *(const float4*)&v[gofs];
            *(float4*)&sr[tt][s4] = *(const float4*)&r[gofs];
        }
        __syncthreads();

        float* outp = r + base + (size_t)t0 * C + s;
#pragma unroll 4
        for (int tt = 0; tt < CH; tt++) {
            float kk = fminf(fmaxf(sk[tt][s], -10.f), 10.f);
            float w  = __expf(kk);
            if (t0 + tt == 0) w *= first;
            num = fmaf(decay, num, w * sv[tt][s]);
            den = fmaf(decay, den, w);
            float rr  = sr[tt][s];
            float sig = 1.f / (1.f + __expf(-rr));
            outp[(size_t)tt * C] = sig * (num / (den + 1e-6f));
        }
    }
}

// ---------------------------------------------------------------------------
extern "C" void kernel_launch(void* const* d_in, const int* in_sizes, int n_in,
                              void* d_out, int out_size)
{
    const float* x  = (const float*)d_in[0];
    const float* Wk = (const float*)d_in[1];
    const float* Wv = (const float*)d_in[2];
    const float* Wr = (const float*)d_in[3];
    const float* Wo = (const float*)d_in[4];
    const float* td = (const float*)d_in[5];
    const float* tf = (const float*)d_in[6];
    float* out = (float*)d_out;

    float *pk, *pv, *pr;
    cudaGetSymbolAddress((void**)&pk, g_k);
    cudaGetSymbolAddress((void**)&pv, g_v);
    cudaGetSymbolAddress((void**)&pr, g_r);

    dim3 grid(NDIM / BN, MDIM / BM);
    dim3 block(256);

    gemm_nt_tf32<<<grid, block>>>(x, Wk, pk, MDIM, NDIM, KDIM);
    gemm_nt_tf32<<<grid, block>>>(x, Wv, pv, MDIM, NDIM, KDIM);
    gemm_nt_tf32<<<grid, block>>>(x, Wr, pr, MDIM, NDIM, KDIM);

    wkv_sigmoid<<<dim3(HH, 4), 128>>>(pk, pv, pr, td, tf);

    gemm_nt_tf32<<<grid, block>>>(pr, Wo, out, MDIM, NDIM, KDIM);
}

// round 4
// speedup vs baseline: 2.6934x; 1.1462x over previous
#include <cuda_runtime.h>
#include <cuda_fp16.h>
#include <cstdint>
#include <cstddef>

// ---------------------------------------------------------------------------
// Problem constants: B=4, T=2048, C=2048, H=16, S=128 ; M = B*T = 8192
// ---------------------------------------------------------------------------
#define MDIM 8192
#define CD   2048
#define HH   16
#define SSZ  128
#define TTL  2048
#define PCH  32          // time chunks for parallel scan
#define LCH  64          // chunk length (PCH*LCH = TTL)

// Scratch (allocation-free: __device__ globals)
__device__ float  g_k [(size_t)MDIM * CD];
__device__ float  g_v [(size_t)MDIM * CD];
__device__ float  g_r [(size_t)MDIM * CD];
__device__ float2 g_st[4 * HH * PCH * SSZ];   // chunk boundary states (num,den)

// ---------------------------------------------------------------------------
// FP16 tensor-core GEMM: C[M,N] = A[M,K] @ B[N,K]^T (row-major, K-contig, f32 in/out)
// Block tile 128x128x32(halves), 256 threads = 8 warps (2M x 4N), warp 64x32.
// mma.sync.m16n8k16.f32.f16.f16.f32. smem stride 40 halves -> conflict-free.
// Double-buffered smem; f32 global loads staged in regs, converted to half2.
// ---------------------------------------------------------------------------
#define BM 128
#define BN 128
#define BKH 32     // K-depth per mainloop iter, in halves (== f32 elements)
#define LDH 40     // smem row stride in halves

#define MMA_F16(d, a, b)                                                   \
    asm volatile(                                                          \
        "mma.sync.aligned.m16n8k16.row.col.f32.f16.f16.f32 "               \
        "{%0,%1,%2,%3}, {%4,%5,%6,%7}, {%8,%9}, {%0,%1,%2,%3};"            \
        : "+f"(d[0]), "+f"(d[1]), "+f"(d[2]), "+f"(d[3])                   \
        : "r"(a[0]), "r"(a[1]), "r"(a[2]), "r"(a[3]), "r"(b[0]), "r"(b[1]))

__device__ __forceinline__ uint2 cvt2h(float4 f) {
    __half2 lo = __floats2half2_rn(f.x, f.y);
    __half2 hi = __floats2half2_rn(f.z, f.w);
    uint2 u;
    u.x = *(uint32_t*)&lo;
    u.y = *(uint32_t*)&hi;
    return u;
}

__global__ __launch_bounds__(256, 2) void gemm_nt_f16(
    const float* __restrict__ A, const float* __restrict__ B,
    float* __restrict__ C, int M, int N, int K)
{
    __shared__ __half As[2][BM * LDH];
    __shared__ __half Bs[2][BN * LDH];

    const int tid  = threadIdx.x;
    const int lane = tid & 31;
    const int wid  = tid >> 5;
    const int wm   = (wid & 1) * 64;
    const int wn   = (wid >> 1) * 32;
    const int g    = lane >> 2;        // 0..7
    const int t4   = lane & 3;         // 0..3

    // loader: thread covers one full row-half: row r0, 16 f32 at col c0
    const int r0 = tid >> 1;           // 0..127
    const int c0 = (tid & 1) * 16;     // 0 or 16

    const float* Ap = A + (size_t)(blockIdx.y * BM + r0) * K + c0;
    const float* Bp = B + (size_t)(blockIdx.x * BN + r0) * K + c0;

    float acc[4][4][4];
#pragma unroll
    for (int mi = 0; mi < 4; mi++)
#pragma unroll
        for (int ni = 0; ni < 4; ni++)
#pragma unroll
            for (int j = 0; j < 4; j++) acc[mi][ni][j] = 0.f;

    uint2 ua[4], ub[4];
#pragma unroll
    for (int j = 0; j < 4; j++) {
        ua[j] = cvt2h(*(const float4*)(Ap + j * 4));
        ub[j] = cvt2h(*(const float4*)(Bp + j * 4));
    }

    const int KT = K / BKH;            // 64
    int s = 0;

    for (int kt = 0; kt < KT; kt++) {
        __half* as = As[s];
        __half* bs = Bs[s];
#pragma unroll
        for (int j = 0; j < 4; j++) {
            *(uint2*)(as + r0 * LDH + c0 + j * 4) = ua[j];
            *(uint2*)(bs + r0 * LDH + c0 + j * 4) = ub[j];
        }
        __syncthreads();

        if (kt + 1 < KT) {
            const int off = (kt + 1) * BKH;
#pragma unroll
            for (int j = 0; j < 4; j++) {
                ua[j] = cvt2h(*(const float4*)(Ap + off + j * 4));
                ub[j] = cvt2h(*(const float4*)(Bp + off + j * 4));
            }
        }

#pragma unroll
        for (int ks = 0; ks < 2; ks++) {     // two k16 sub-steps
            const int k0 = ks * 16;
            uint32_t af[4][4];
            uint32_t bf[4][2];
#pragma unroll
            for (int mi = 0; mi < 4; mi++) {
                const int ra = wm + mi * 16 + g;
                af[mi][0] = *(const uint32_t*)(as + (ra)     * LDH + k0 + 2 * t4);
                af[mi][1] = *(const uint32_t*)(as + (ra + 8) * LDH + k0 + 2 * t4);
                af[mi][2] = *(const uint32_t*)(as + (ra)     * LDH + k0 + 8 + 2 * t4);
                af[mi][3] = *(const uint32_t*)(as + (ra + 8) * LDH + k0 + 8 + 2 * t4);
            }
#pragma unroll
            for (int ni = 0; ni < 4; ni++) {
                const int cn = wn + ni * 8 + g;
                bf[ni][0] = *(const uint32_t*)(bs + cn * LDH + k0 + 2 * t4);
                bf[ni][1] = *(const uint32_t*)(bs + cn * LDH + k0 + 8 + 2 * t4);
            }
#pragma unroll
            for (int mi = 0; mi < 4; mi++)
#pragma unroll
                for (int ni = 0; ni < 4; ni++)
                    MMA_F16(acc[mi][ni], af[mi], bf[ni]);
        }
        __syncthreads();
        s ^= 1;
    }

    // epilogue: fragment -> global (float2 per quad, coalesced)
#pragma unroll
    for (int mi = 0; mi < 4; mi++) {
#pragma unroll
        for (int ni = 0; ni < 4; ni++) {
            const int row = blockIdx.y * BM + wm + mi * 16 + g;
            const int col = blockIdx.x * BN + wn + ni * 8 + 2 * t4;
            *(float2*)&C[(size_t)row * N + col] =
                make_float2(acc[mi][ni][0], acc[mi][ni][1]);
            *(float2*)&C[(size_t)(row + 8) * N + col] =
                make_float2(acc[mi][ni][2], acc[mi][ni][3]);
        }
    }
}

// ---------------------------------------------------------------------------
// WKV chunk-parallel scan (3 passes). num=decay*num+w*v; den=decay*den+w,
// decay constant per (h,s) -> linear recurrence, chunkable.
// ---------------------------------------------------------------------------
__global__ __launch_bounds__(128) void wkv_p1(
    const float* __restrict__ k, const float* __restrict__ v,
    const float* __restrict__ td, const float* __restrict__ tf)
{
    const int s = threadIdx.x, p = blockIdx.x, h = blockIdx.y, b = blockIdx.z;
    const float decay = expf(-expf(td[h * SSZ + s]));
    const float first = expf(tf[h * SSZ + s]);
    size_t base = ((size_t)(b * TTL + p * LCH)) * CD + h * SSZ + s;
    float num = 0.f, den = 0.f;
#pragma unroll 4
    for (int i = 0; i < LCH; i++) {
        float kk = fminf(fmaxf(k[base], -10.f), 10.f);
        float w  = __expf(kk);
        if (p == 0 && i == 0) w *= first;
        num = fmaf(decay, num, w * v[base]);
        den = fmaf(decay, den, w);
        base += CD;
    }
    g_st[(((size_t)b * HH + h) * PCH + p) * SSZ + s] = make_float2(num, den);
}

__global__ __launch_bounds__(128) void wkv_p2(const float* __restrict__ td)
{
    const int s = threadIdx.x, h = blockIdx.x, b = blockIdx.y;
    const float dC = expf(-(float)LCH * expf(td[h * SSZ + s]));  // decay^LCH
    float2 run = make_float2(0.f, 0.f);
    size_t base = ((size_t)b * HH + h) * PCH;
    for (int p = 0; p < PCH; p++) {
        size_t idx = (base + p) * SSZ + s;
        float2 cur = g_st[idx];
        g_st[idx]  = run;                    // exclusive prefix state
        run.x = fmaf(dC, run.x, cur.x);
        run.y = fmaf(dC, run.y, cur.y);
    }
}

// Pass 3: replay with carried state; gate with sigmoid(r); write f32 in-place.
__global__ __launch_bounds__(128) void wkv_p3(
    const float* __restrict__ k, const float* __restrict__ v,
    float* __restrict__ r,
    const float* __restrict__ td, const float* __restrict__ tf)
{
    const int s = threadIdx.x, p = blockIdx.x, h = blockIdx.y, b = blockIdx.z;
    const float decay = expf(-expf(td[h * SSZ + s]));
    const float first = expf(tf[h * SSZ + s]);
    float2 st = g_st[(((size_t)b * HH + h) * PCH + p) * SSZ + s];
    float num = st.x, den = st.y;
    size_t base = ((size_t)(b * TTL + p * LCH)) * CD + h * SSZ + s;
#pragma unroll 4
    for (int i = 0; i < LCH; i++) {
        float kk = fminf(fmaxf(k[base], -10.f), 10.f);
        float w  = __expf(kk);
        if (p == 0 && i == 0) w *= first;
        num = fmaf(decay, num, w * v[base]);
        den = fmaf(decay, den, w);
        float rr  = r[base];
        float sig = 1.f / (1.f + __expf(-rr));
        r[base] = sig * (num / (den + 1e-6f));
        base += CD;
    }
}

// ---------------------------------------------------------------------------
extern "C" void kernel_launch(void* const* d_in, const int* in_sizes, int n_in,
                              void* d_out, int out_size)
{
    const float* x  = (const float*)d_in[0];
    const float* Wk = (const float*)d_in[1];
    const float* Wv = (const float*)d_in[2];
    const float* Wr = (const float*)d_in[3];
    const float* Wo = (const float*)d_in[4];
    const float* td = (const float*)d_in[5];
    const float* tf = (const float*)d_in[6];
    float* out = (float*)d_out;

    float *pk, *pv, *pr;
    cudaGetSymbolAddress((void**)&pk, g_k);
    cudaGetSymbolAddress((void**)&pv, g_v);
    cudaGetSymbolAddress((void**)&pr, g_r);

    dim3 grid(CD / BN, MDIM / BM);    // (16, 64)
    dim3 block(256);

    gemm_nt_f16<<<grid, block>>>(x, Wk, pk, MDIM, CD, CD);
    gemm_nt_f16<<<grid, block>>>(x, Wv, pv, MDIM, CD, CD);
    gemm_nt_f16<<<grid, block>>>(x, Wr, pr, MDIM, CD, CD);

    wkv_p1<<<dim3(PCH, HH, 4), 128>>>(pk, pv, td, tf);
    wkv_p2<<<dim3(HH, 4), 128>>>(td);
    wkv_p3<<<dim3(PCH, HH, 4), 128>>>(pk, pv, pr, td, tf);

    gemm_nt_f16<<<grid, block>>>(pr, Wo, out, MDIM, CD, CD);
}

// round 5
// speedup vs baseline: 5.2711x; 1.9570x over previous
#include <cuda_runtime.h>
#include <cuda_fp16.h>
#include <cstdint>
#include <cstddef>

// ---------------------------------------------------------------------------
// Problem constants: B=4, T=2048, C=2048, H=16, S=128 ; M = B*T = 8192
// ---------------------------------------------------------------------------
#define MDIM 8192
#define CD   2048
#define HH   16
#define SSZ  128
#define TTL  2048
#define PCH  32          // time chunks for parallel scan
#define LCH  64          // chunk length (PCH*LCH = TTL)

// Scratch (allocation-free: __device__ globals)
__device__ __half g_xp [(size_t)MDIM * CD];   // x in fp16
__device__ __half g_wkp[(size_t)CD * CD];
__device__ __half g_wvp[(size_t)CD * CD];
__device__ __half g_wrp[(size_t)CD * CD];
__device__ __half g_wop[(size_t)CD * CD];
__device__ __half g_gp [(size_t)MDIM * CD];   // gated sigmoid(r)*wkv in fp16
__device__ float  g_k  [(size_t)MDIM * CD];
__device__ float  g_v  [(size_t)MDIM * CD];
__device__ float  g_r  [(size_t)MDIM * CD];
__device__ float2 g_st [4 * HH * PCH * SSZ];  // chunk boundary states

// ---------------------------------------------------------------------------
// helpers
// ---------------------------------------------------------------------------
__device__ __forceinline__ uint32_t smem_u32(const void* p) {
    uint32_t a;
    asm("{ .reg .u64 t; cvta.to.shared.u64 t, %1; cvt.u32.u64 %0, t; }"
        : "=r"(a) : "l"(p));
    return a;
}
__device__ __forceinline__ void cp16(uint32_t dst, const void* src) {
    asm volatile("cp.async.cg.shared.global [%0], [%1], 16;"
                 :: "r"(dst), "l"(src) : "memory");
}
#define CP_COMMIT() asm volatile("cp.async.commit_group;" ::: "memory")
#define CP_WAIT(n)  asm volatile("cp.async.wait_group %0;" :: "n"(n) : "memory")

#define LDSM4(r0, r1, r2, r3, addr)                                        \
    asm volatile("ldmatrix.sync.aligned.m8n8.x4.shared.b16 "               \
                 "{%0,%1,%2,%3}, [%4];"                                    \
                 : "=r"(r0), "=r"(r1), "=r"(r2), "=r"(r3) : "r"(addr))

#define MMA_F16(d, a, b)                                                   \
    asm volatile(                                                          \
        "mma.sync.aligned.m16n8k16.row.col.f32.f16.f16.f32 "               \
        "{%0,%1,%2,%3}, {%4,%5,%6,%7}, {%8,%9}, {%0,%1,%2,%3};"            \
        : "+f"(d[0]), "+f"(d[1]), "+f"(d[2]), "+f"(d[3])                   \
        : "r"(a[0]), "r"(a[1]), "r"(a[2]), "r"(a[3]), "r"(b[0]), "r"(b[1]))

// ---------------------------------------------------------------------------
// pack: f32 -> fp16, contiguous (float4 -> 2x half2)
// ---------------------------------------------------------------------------
__global__ __launch_bounds__(256) void pack_h(
    const float* __restrict__ src, __half* __restrict__ dst, long n4)
{
    long i = (long)blockIdx.x * blockDim.x + threadIdx.x;
    if (i >= n4) return;
    float4 f = ((const float4*)src)[i];
    __half2* d = (__half2*)dst + 2 * i;
    d[0] = __floats2half2_rn(f.x, f.y);
    d[1] = __floats2half2_rn(f.z, f.w);
}

// ---------------------------------------------------------------------------
// FP16 tensor GEMM: C[M,N] = A[M,K] @ B[N,K]^T, fp16 in, f32 out.
// Block 128x128x32, 256 threads = 8 warps (2M x 4N), warp 64x32.
// cp.async double-buffered smem (stride 40 halves = 80B, 16B-aligned rows,
// 5r mod 8 -> conflict-free for both cp.async and ldmatrix), ldmatrix frags.
// ---------------------------------------------------------------------------
#define LDH 40
#define BUFB (128 * LDH * 2)   // bytes per buffer

__global__ __launch_bounds__(256, 2) void gemm_nt_h(
    const __half* __restrict__ A, const __half* __restrict__ B,
    float* __restrict__ C, int M, int N, int K)
{
    __shared__ __half As[2][128 * LDH];
    __shared__ __half Bs[2][128 * LDH];
    const uint32_t sA = smem_u32(As);
    const uint32_t sB = smem_u32(Bs);

    const int tid  = threadIdx.x;
    const int lane = tid & 31;
    const int wid  = tid >> 5;
    const int wm   = (wid & 1) * 64;
    const int wn   = (wid >> 1) * 32;
    const int g    = lane >> 2;
    const int t4   = lane & 3;

    // loader mapping: thread -> rows lr, lr+64 ; 16B chunk lu
    const int lr = tid >> 2;
    const int lu = tid & 3;
    const __half* Ap0 = A + (size_t)(blockIdx.y * 128 + lr) * K + lu * 8;
    const __half* Ap1 = Ap0 + (size_t)64 * K;
    const __half* Bp0 = B + (size_t)(blockIdx.x * 128 + lr) * K + lu * 8;
    const __half* Bp1 = Bp0 + (size_t)64 * K;
    const uint32_t da0 = sA + lr * 80 + lu * 16, da1 = da0 + 64 * 80;
    const uint32_t db0 = sB + lr * 80 + lu * 16, db1 = db0 + 64 * 80;

    // ldmatrix per-lane addresses (bytes)
    const uint32_t a_base = sA + ((wm + (lane & 15)) * LDH + ((lane >> 4) << 3)) * 2;
    const uint32_t b_base = sB + ((wn + (lane & 7) + ((lane >> 4) & 1) * 8) * LDH
                                  + (((lane >> 3) & 1) << 3)) * 2;

    float acc[4][4][4];
#pragma unroll
    for (int mi = 0; mi < 4; mi++)
#pragma unroll
        for (int ni = 0; ni < 4; ni++)
#pragma unroll
            for (int j = 0; j < 4; j++) acc[mi][ni][j] = 0.f;

    const int KT = K / 32;   // 64

    // prefetch tile 0
    {
        cp16(da0, Ap0); cp16(da1, Ap1);
        cp16(db0, Bp0); cp16(db1, Bp1);
        CP_COMMIT();
    }

    for (int kt = 0; kt < KT; kt++) {
        const int s = kt & 1;
        if (kt + 1 < KT) {
            const uint32_t o = (uint32_t)((s ^ 1) * BUFB);
            const int koff = (kt + 1) * 32;
            cp16(da0 + o, Ap0 + koff); cp16(da1 + o, Ap1 + koff);
            cp16(db0 + o, Bp0 + koff); cp16(db1 + o, Bp1 + koff);
            CP_COMMIT();
            CP_WAIT(1);
        } else {
            CP_WAIT(0);
        }
        __syncthreads();

        const uint32_t so = (uint32_t)(s * BUFB);
#pragma unroll
        for (int ks = 0; ks < 2; ks++) {
            const uint32_t ko = ks * 32;   // 16 halves = 32 bytes
            uint32_t af[4][4];
            uint32_t bf[4][2];
#pragma unroll
            for (int mi = 0; mi < 4; mi++)
                LDSM4(af[mi][0], af[mi][1], af[mi][2], af[mi][3],
                      a_base + so + mi * (16 * 80) + ko);
#pragma unroll
            for (int pr = 0; pr < 2; pr++)
                LDSM4(bf[2 * pr][0], bf[2 * pr][1], bf[2 * pr + 1][0], bf[2 * pr + 1][1],
                      b_base + so + pr * (16 * 80) + ko);
#pragma unroll
            for (int mi = 0; mi < 4; mi++)
#pragma unroll
                for (int ni = 0; ni < 4; ni++)
                    MMA_F16(acc[mi][ni], af[mi], bf[ni]);
        }
        __syncthreads();
    }

    // epilogue
#pragma unroll
    for (int mi = 0; mi < 4; mi++) {
#pragma unroll
        for (int ni = 0; ni < 4; ni++) {
            const int row = blockIdx.y * 128 + wm + mi * 16 + g;
            const int col = blockIdx.x * 128 + wn + ni * 8 + 2 * t4;
            *(float2*)&C[(size_t)row * N + col] =
                make_float2(acc[mi][ni][0], acc[mi][ni][1]);
            *(float2*)&C[(size_t)(row + 8) * N + col] =
                make_float2(acc[mi][ni][2], acc[mi][ni][3]);
        }
    }
}

// ---------------------------------------------------------------------------
// WKV chunk-parallel scan (3 passes); pass 3 gates + writes fp16 directly.
// ---------------------------------------------------------------------------
__global__ __launch_bounds__(128) void wkv_p1(
    const float* __restrict__ k, const float* __restrict__ v,
    const float* __restrict__ td, const float* __restrict__ tf)
{
    const int s = threadIdx.x, p = blockIdx.x, h = blockIdx.y, b = blockIdx.z;
    const float decay = expf(-expf(td[h * SSZ + s]));
    const float first = expf(tf[h * SSZ + s]);
    size_t base = ((size_t)(b * TTL + p * LCH)) * CD + h * SSZ + s;
    float num = 0.f, den = 0.f;
#pragma unroll 4
    for (int i = 0; i < LCH; i++) {
        float kk = fminf(fmaxf(k[base], -10.f), 10.f);
        float w  = __expf(kk);
        if (p == 0 && i == 0) w *= first;
        num = fmaf(decay, num, w * v[base]);
        den = fmaf(decay, den, w);
        base += CD;
    }
    g_st[(((size_t)b * HH + h) * PCH + p) * SSZ + s] = make_float2(num, den);
}

__global__ __launch_bounds__(128) void wkv_p2(const float* __restrict__ td)
{
    const int s = threadIdx.x, h = blockIdx.x, b = blockIdx.y;
    const float dC = expf(-(float)LCH * expf(td[h * SSZ + s]));
    float2 run = make_float2(0.f, 0.f);
    size_t base = ((size_t)b * HH + h) * PCH;
    for (int p = 0; p < PCH; p++) {
        size_t idx = (base + p) * SSZ + s;
        float2 cur = g_st[idx];
        g_st[idx]  = run;
        run.x = fmaf(dC, run.x, cur.x);
        run.y = fmaf(dC, run.y, cur.y);
    }
}

__global__ __launch_bounds__(128) void wkv_p3(
    const float* __restrict__ k, const float* __restrict__ v,
    const float* __restrict__ r,
    const float* __restrict__ td, const float* __restrict__ tf)
{
    const int s = threadIdx.x, p = blockIdx.x, h = blockIdx.y, b = blockIdx.z;
    const float decay = expf(-expf(td[h * SSZ + s]));
    const float first = expf(tf[h * SSZ + s]);
    float2 st = g_st[(((size_t)b * HH + h) * PCH + p) * SSZ + s];
    float num = st.x, den = st.y;
    const int c = h * SSZ + s;
    size_t base = ((size_t)(b * TTL + p * LCH)) * CD + c;
#pragma unroll 4
    for (int i = 0; i < LCH; i++) {
        float kk = fminf(fmaxf(k[base], -10.f), 10.f);
        float w  = __expf(kk);
        if (p == 0 && i == 0) w *= first;
        num = fmaf(decay, num, w * v[base]);
        den = fmaf(decay, den, w);
        float rr  = r[base];
        float sig = 1.f / (1.f + __expf(-rr));
        g_gp[base] = __float2half_rn(sig * (num / (den + 1e-6f)));
        base += CD;
    }
}

// ---------------------------------------------------------------------------
extern "C" void kernel_launch(void* const* d_in, const int* in_sizes, int n_in,
                              void* d_out, int out_size)
{
    const float* x  = (const float*)d_in[0];
    const float* Wk = (const float*)d_in[1];
    const float* Wv = (const float*)d_in[2];
    const float* Wr = (const float*)d_in[3];
    const float* Wo = (const float*)d_in[4];
    const float* td = (const float*)d_in[5];
    const float* tf = (const float*)d_in[6];
    float* out = (float*)d_out;

    __half *xp, *wkp, *wvp, *wrp, *wop, *gp;
    float *pk, *pv, *pr;
    cudaGetSymbolAddress((void**)&xp,  g_xp);
    cudaGetSymbolAddress((void**)&wkp, g_wkp);
    cudaGetSymbolAddress((void**)&wvp, g_wvp);
    cudaGetSymbolAddress((void**)&wrp, g_wrp);
    cudaGetSymbolAddress((void**)&wop, g_wop);
    cudaGetSymbolAddress((void**)&gp,  g_gp);
    cudaGetSymbolAddress((void**)&pk,  g_k);
    cudaGetSymbolAddress((void**)&pv,  g_v);
    cudaGetSymbolAddress((void**)&pr,  g_r);

    // packs: f32 -> fp16
    const long nx4 = (long)MDIM * CD / 4;
    const long nw4 = (long)CD * CD / 4;
    pack_h<<<(unsigned)((nx4 + 255) / 256), 256>>>(x,  xp,  nx4);
    pack_h<<<(unsigned)((nw4 + 255) / 256), 256>>>(Wk, wkp, nw4);
    pack_h<<<(unsigned)((nw4 + 255) / 256), 256>>>(Wv, wvp, nw4);
    pack_h<<<(unsigned)((nw4 + 255) / 256), 256>>>(Wr, wrp, nw4);
    pack_h<<<(unsigned)((nw4 + 255) / 256), 256>>>(Wo, wop, nw4);

    dim3 grid(CD / 128, MDIM / 128);    // (16, 64)
    dim3 block(256);

    gemm_nt_h<<<grid, block>>>(xp, wkp, pk, MDIM, CD, CD);
    gemm_nt_h<<<grid, block>>>(xp, wvp, pv, MDIM, CD, CD);
    gemm_nt_h<<<grid, block>>>(xp, wrp, pr, MDIM, CD, CD);

    wkv_p1<<<dim3(PCH, HH, 4), 128>>>(pk, pv, td, tf);
    wkv_p2<<<dim3(HH, 4), 128>>>(td);
    wkv_p3<<<dim3(PCH, HH, 4), 128>>>(pk, pv, pr, td, tf);

    gemm_nt_h<<<grid, block>>>(gp, wop, out, MDIM, CD, CD);
}

// round 6
// speedup vs baseline: 6.2958x; 1.1944x over previous
#include <cuda_runtime.h>
#include <cuda_fp16.h>
#include <cstdint>
#include <cstddef>

// ---------------------------------------------------------------------------
// Problem constants: B=4, T=2048, C=2048, H=16, S=128 ; M = B*T = 8192
// ---------------------------------------------------------------------------
#define MDIM 8192
#define CD   2048
#define HH   16
#define SSZ  128
#define TTL  2048
#define PCH  32
#define LCH  64

// Scratch (allocation-free: __device__ globals)
__device__ __half g_xp  [(size_t)MDIM * CD];      // x fp16
__device__ __half g_wkvr[(size_t)3 * CD * CD];    // concat(Wk,Wv,Wr) fp16
__device__ __half g_wop [(size_t)CD * CD];        // Wo fp16
__device__ __half g_gp  [(size_t)MDIM * CD];      // gated output fp16
__device__ float  g_k   [(size_t)MDIM * CD];
__device__ float  g_v   [(size_t)MDIM * CD];
__device__ float  g_r   [(size_t)MDIM * CD];
__device__ float2 g_st  [4 * HH * PCH * SSZ];

// ---------------------------------------------------------------------------
// helpers
// ---------------------------------------------------------------------------
__device__ __forceinline__ uint32_t smem_u32(const void* p) {
    uint32_t a;
    asm("{ .reg .u64 t; cvta.to.shared.u64 t, %1; cvt.u32.u64 %0, t; }"
        : "=r"(a) : "l"(p));
    return a;
}
__device__ __forceinline__ void cp16(uint32_t dst, const void* src) {
    asm volatile("cp.async.cg.shared.global [%0], [%1], 16;"
                 :: "r"(dst), "l"(src) : "memory");
}
#define CP_COMMIT() asm volatile("cp.async.commit_group;" ::: "memory")
#define CP_WAIT(n)  asm volatile("cp.async.wait_group %0;" :: "n"(n) : "memory")

#define LDSM4(r0, r1, r2, r3, addr)                                        \
    asm volatile("ldmatrix.sync.aligned.m8n8.x4.shared.b16 "               \
                 "{%0,%1,%2,%3}, [%4];"                                    \
                 : "=r"(r0), "=r"(r1), "=r"(r2), "=r"(r3) : "r"(addr))

#define MMA_F16(d, a, b)                                                   \
    asm volatile(                                                          \
        "mma.sync.aligned.m16n8k16.row.col.f32.f16.f16.f32 "               \
        "{%0,%1,%2,%3}, {%4,%5,%6,%7}, {%8,%9}, {%0,%1,%2,%3};"            \
        : "+f"(d[0]), "+f"(d[1]), "+f"(d[2]), "+f"(d[3])                   \
        : "r"(a[0]), "r"(a[1]), "r"(a[2]), "r"(a[3]), "r"(b[0]), "r"(b[1]))

// ---------------------------------------------------------------------------
// pack-all: x + 4 weights -> fp16, one launch
// ---------------------------------------------------------------------------
#define NX4 ((long)MDIM * CD / 4)     // 4,194,304
#define NW4 ((long)CD * CD / 4)       // 1,048,576

__global__ __launch_bounds__(256) void pack_all(
    const float* __restrict__ x,  const float* __restrict__ Wk,
    const float* __restrict__ Wv, const float* __restrict__ Wr,
    const float* __restrict__ Wo,
    __half* __restrict__ xp, __half* __restrict__ wkvr, __half* __restrict__ wop)
{
    long i = (long)blockIdx.x * blockDim.x + threadIdx.x;
    const float* src;
    __half* dst;
    long j;
    if (i < NX4) {
        src = x; dst = xp; j = i;
    } else {
        long i2 = i - NX4;
        int  w  = (int)(i2 / NW4);
        j = i2 - (long)w * NW4;
        if      (w == 0) { src = Wk; dst = wkvr; }
        else if (w == 1) { src = Wv; dst = wkvr + (size_t)CD * CD; }
        else if (w == 2) { src = Wr; dst = wkvr + (size_t)2 * CD * CD; }
        else             { src = Wo; dst = wop; }
    }
    float4 f = ((const float4*)src)[j];
    __half2* d = (__half2*)dst + 2 * j;
    d[0] = __floats2half2_rn(f.x, f.y);
    d[1] = __floats2half2_rn(f.z, f.w);
}

// ---------------------------------------------------------------------------
// FP16 tensor GEMM: C[M,N] = A[M,K] @ B[N,K]^T, fp16 in, f32 out.
// Block 128x128x32, 256 thr = 8 warps (2M x 4N). 3-stage cp.async pipeline,
// ONE __syncthreads per iter. ldmatrix fragments. Optional split output:
// if NSPLIT>0, output column-block bx selects buffer C[bx/NSPLIT] with
// row stride CD (used for the fused k/v/r GEMM).
// ---------------------------------------------------------------------------
#define LDH 40
#define BUFB (128 * LDH * 2)          // 10240 B per operand per stage
#define SMEM_GEMM (6 * BUFB)          // 3 stages x 2 operands = 61440 B

__global__ __launch_bounds__(256, 2) void gemm_nt_h(
    const __half* __restrict__ A, const __half* __restrict__ B,
    float* __restrict__ C0, float* __restrict__ C1, float* __restrict__ C2,
    int K, int nsplit)
{
    extern __shared__ __align__(16) char dyn_smem[];
    const uint32_t sA = smem_u32(dyn_smem);
    const uint32_t sB = sA + 3 * BUFB;

    const int tid  = threadIdx.x;
    const int lane = tid & 31;
    const int wid  = tid >> 5;
    const int wm   = (wid & 1) * 64;
    const int wn   = (wid >> 1) * 32;
    const int g    = lane >> 2;
    const int t4   = lane & 3;

    const int lr = tid >> 2;
    const int lu = tid & 3;
    const __half* Ap0 = A + (size_t)(blockIdx.y * 128 + lr) * K + lu * 8;
    const __half* Ap1 = Ap0 + (size_t)64 * K;
    const __half* Bp0 = B + (size_t)(blockIdx.x * 128 + lr) * K + lu * 8;
    const __half* Bp1 = Bp0 + (size_t)64 * K;
    const uint32_t da0 = sA + lr * 80 + lu * 16, da1 = da0 + 64 * 80;
    const uint32_t db0 = sB + lr * 80 + lu * 16, db1 = db0 + 64 * 80;

    const uint32_t a_base = sA + ((wm + (lane & 15)) * LDH + ((lane >> 4) << 3)) * 2;
    const uint32_t b_base = sB + ((wn + (lane & 7) + ((lane >> 4) & 1) * 8) * LDH
                                  + (((lane >> 3) & 1) << 3)) * 2;

    float acc[4][4][4];
#pragma unroll
    for (int mi = 0; mi < 4; mi++)
#pragma unroll
        for (int ni = 0; ni < 4; ni++)
#pragma unroll
            for (int j = 0; j < 4; j++) acc[mi][ni][j] = 0.f;

    const int KT = K / 32;   // 64

    // prologue: prefetch tiles 0 and 1
#pragma unroll
    for (int pf = 0; pf < 2; pf++) {
        const uint32_t o = (uint32_t)(pf * BUFB);
        const int koff = pf * 32;
        cp16(da0 + o, Ap0 + koff); cp16(da1 + o, Ap1 + koff);
        cp16(db0 + o, Bp0 + koff); cp16(db1 + o, Bp1 + koff);
        CP_COMMIT();
    }

    int st = 0;                       // stage of tile kt
    for (int kt = 0; kt < KT; kt++) {
        if (kt + 1 < KT) { CP_WAIT(1); } else { CP_WAIT(0); }
        __syncthreads();

        const uint32_t so = (uint32_t)(st * BUFB);
#pragma unroll
        for (int ks = 0; ks < 2; ks++) {
            const uint32_t ko = ks * 32;
            uint32_t af[4][4];
            uint32_t bf[4][2];
#pragma unroll
            for (int mi = 0; mi < 4; mi++)
                LDSM4(af[mi][0], af[mi][1], af[mi][2], af[mi][3],
                      a_base + so + mi * (16 * 80) + ko);
#pragma unroll
            for (int pr = 0; pr < 2; pr++)
                LDSM4(bf[2 * pr][0], bf[2 * pr][1], bf[2 * pr + 1][0], bf[2 * pr + 1][1],
                      b_base + so + pr * (16 * 80) + ko);
#pragma unroll
            for (int mi = 0; mi < 4; mi++)
#pragma unroll
                for (int ni = 0; ni < 4; ni++)
                    MMA_F16(acc[mi][ni], af[mi], bf[ni]);
        }

        if (kt + 2 < KT) {
            const int ns = (st + 2 > 2) ? (st - 1) : (st + 2);
            const uint32_t o = (uint32_t)(ns * BUFB);
            const int koff = (kt + 2) * 32;
            cp16(da0 + o, Ap0 + koff); cp16(da1 + o, Ap1 + koff);
            cp16(db0 + o, Bp0 + koff); cp16(db1 + o, Bp1 + koff);
            CP_COMMIT();
        }
        st = (st + 1 > 2) ? 0 : (st + 1);
    }

    // epilogue: select output buffer for split (fused) mode
    float* C = C0;
    int cbx = blockIdx.x;
    if (nsplit > 0) {
        const int which = blockIdx.x / nsplit;
        C = (which == 0) ? C0 : ((which == 1) ? C1 : C2);
        cbx = blockIdx.x - which * nsplit;
    }
#pragma unroll
    for (int mi = 0; mi < 4; mi++) {
#pragma unroll
        for (int ni = 0; ni < 4; ni++) {
            const int row = blockIdx.y * 128 + wm + mi * 16 + g;
            const int col = cbx * 128 + wn + ni * 8 + 2 * t4;
            *(float2*)&C[(size_t)row * CD + col] =
                make_float2(acc[mi][ni][0], acc[mi][ni][1]);
            *(float2*)&C[(size_t)(row + 8) * CD + col] =
                make_float2(acc[mi][ni][2], acc[mi][ni][3]);
        }
    }
}

// ---------------------------------------------------------------------------
// WKV chunk-parallel scan (3 passes); pass 3 gates + writes fp16 directly.
// ---------------------------------------------------------------------------
__global__ __launch_bounds__(128) void wkv_p1(
    const float* __restrict__ k, const float* __restrict__ v,
    const float* __restrict__ td, const float* __restrict__ tf)
{
    const int s = threadIdx.x, p = blockIdx.x, h = blockIdx.y, b = blockIdx.z;
    const float decay = expf(-expf(td[h * SSZ + s]));
    const float first = expf(tf[h * SSZ + s]);
    size_t base = ((size_t)(b * TTL + p * LCH)) * CD + h * SSZ + s;
    float num = 0.f, den = 0.f;
#pragma unroll 4
    for (int i = 0; i < LCH; i++) {
        float kk = fminf(fmaxf(k[base], -10.f), 10.f);
        float w  = __expf(kk);
        if (p == 0 && i == 0) w *= first;
        num = fmaf(decay, num, w * v[base]);
        den = fmaf(decay, den, w);
        base += CD;
    }
    g_st[(((size_t)b * HH + h) * PCH + p) * SSZ + s] = make_float2(num, den);
}

__global__ __launch_bounds__(128) void wkv_p2(const float* __restrict__ td)
{
    const int s = threadIdx.x, h = blockIdx.x, b = blockIdx.y;
    const float dC = expf(-(float)LCH * expf(td[h * SSZ + s]));
    float2 run = make_float2(0.f, 0.f);
    size_t base = ((size_t)b * HH + h) * PCH;
    for (int p = 0; p < PCH; p++) {
        size_t idx = (base + p) * SSZ + s;
        float2 cur = g_st[idx];
        g_st[idx]  = run;
        run.x = fmaf(dC, run.x, cur.x);
        run.y = fmaf(dC, run.y, cur.y);
    }
}

__global__ __launch_bounds__(128) void wkv_p3(
    const float* __restrict__ k, const float* __restrict__ v,
    const float* __restrict__ r,
    const float* __restrict__ td, const float* __restrict__ tf)
{
    const int s = threadIdx.x, p = blockIdx.x, h = blockIdx.y, b = blockIdx.z;
    const float decay = expf(-expf(td[h * SSZ + s]));
    const float first = expf(tf[h * SSZ + s]);
    float2 st = g_st[(((size_t)b * HH + h) * PCH + p) * SSZ + s];
    float num = st.x, den = st.y;
    size_t base = ((size_t)(b * TTL + p * LCH)) * CD + h * SSZ + s;
#pragma unroll 4
    for (int i = 0; i < LCH; i++) {
        float kk = fminf(fmaxf(k[base], -10.f), 10.f);
        float w  = __expf(kk);
        if (p == 0 && i == 0) w *= first;
        num = fmaf(decay, num, w * v[base]);
        den = fmaf(decay, den, w);
        float rr  = r[base];
        float sig = 1.f / (1.f + __expf(-rr));
        g_gp[base] = __float2half_rn(sig * (num / (den + 1e-6f)));
        base += CD;
    }
}

// ---------------------------------------------------------------------------
extern "C" void kernel_launch(void* const* d_in, const int* in_sizes, int n_in,
                              void* d_out, int out_size)
{
    const float* x  = (const float*)d_in[0];
    const float* Wk = (const float*)d_in[1];
    const float* Wv = (const float*)d_in[2];
    const float* Wr = (const float*)d_in[3];
    const float* Wo = (const float*)d_in[4];
    const float* td = (const float*)d_in[5];
    const float* tf = (const float*)d_in[6];
    float* out = (float*)d_out;

    __half *xp, *wkvr, *wop, *gp;
    float *pk, *pv, *pr;
    cudaGetSymbolAddress((void**)&xp,   g_xp);
    cudaGetSymbolAddress((void**)&wkvr, g_wkvr);
    cudaGetSymbolAddress((void**)&wop,  g_wop);
    cudaGetSymbolAddress((void**)&gp,   g_gp);
    cudaGetSymbolAddress((void**)&pk,   g_k);
    cudaGetSymbolAddress((void**)&pv,   g_v);
    cudaGetSymbolAddress((void**)&pr,   g_r);

    cudaFuncSetAttribute(gemm_nt_h, cudaFuncAttributeMaxDynamicSharedMemorySize,
                         SMEM_GEMM);

    // single pack launch: x + Wk + Wv + Wr + Wo
    const long nAll = NX4 + 4 * NW4;     // 8,388,608 threads
    pack_all<<<(unsigned)((nAll + 255) / 256), 256>>>(
        x, Wk, Wv, Wr, Wo, xp, wkvr, wop);

    // fused k/v/r GEMM: N = 3*2048, output split across 3 buffers
    dim3 gridF(3 * CD / 128, MDIM / 128);   // (48, 64)
    gemm_nt_h<<<gridF, 256, SMEM_GEMM>>>(xp, wkvr, pk, pv, pr, CD, CD / 128);

    wkv_p1<<<dim3(PCH, HH, 4), 128>>>(pk, pv, td, tf);
    wkv_p2<<<dim3(HH, 4), 128>>>(td);
    wkv_p3<<<dim3(PCH, HH, 4), 128>>>(pk, pv, pr, td, tf);

    // output GEMM
    dim3 gridO(CD / 128, MDIM / 128);       // (16, 64)
    gemm_nt_h<<<gridO, 256, SMEM_GEMM>>>(gp, wop, out, nullptr, nullptr, CD, 0);
}